// round 1
// baseline (speedup 1.0000x reference)
#include <cuda_runtime.h>
#include <math.h>

// ---------------- problem constants ----------------
namespace {
constexpr int NN   = 30000;   // nodes
constexpr int NE   = 480000;  // edges
constexpr int C    = 128;     // channels (= F)
constexpr int KG   = 8;       // gaussians
constexpr int LL   = 4;       // layers
constexpr int H    = 256;     // LSTM hidden
constexpr int H4   = 1024;    // 4*H
constexpr int NHID = 512;
constexpr int NOUT = 256;
constexpr int NB   = 1024;    // graphs
}

// ---------------- scratch (device globals; no allocations allowed) -------
__device__ __align__(256) float d_h[NN * C];
__device__ __align__(256) float d_hl[LL][NN * C];
__device__ __align__(256) float d_xg[NN * KG * C];
__device__ __align__(256) float d_ew[NE * KG];
__device__ __align__(256) float d_deg[NN];
__device__ __align__(256) float d_agg[NN * C];
__device__ __align__(256) float d_hr[NN * C];
__device__ __align__(256) float d_bns[C];
__device__ __align__(256) float d_bnq[C];
__device__ __align__(256) float d_gates[NN * H4];
__device__ __align__(256) float d_lh[NN * H];
__device__ __align__(256) float d_lc[NN * H];
__device__ __align__(256) float d_af[5 * NN];
__device__ __align__(256) float d_ab[5 * NN];
__device__ __align__(256) float d_nrep[NN * C];
__device__ __align__(256) float d_cnt[NB];
__device__ __align__(256) float d_hg[NB * C];
__device__ __align__(256) float d_z1[NB * NHID];
__device__ __align__(256) float d_z2[NB * NOUT];

// ---------------- generic tiled SGEMM ----------------
// C[M,N] = A[M,K] @ (TB ? B[N,K]^T : B[K,N])  (+C if ACC) (+bias[n] if BIAS) (relu if RELU)
// requires: K % 8 == 0, N % 128 == 0. M arbitrary.
template <bool TB, bool ACC, bool RELU_, bool BIAS_>
__global__ __launch_bounds__(256) void sgemm(
    const float* __restrict__ A, const float* __restrict__ B,
    float* __restrict__ Cm, const float* __restrict__ bias,
    int M, int Nm, int Kd)
{
    __shared__ __align__(16) float As[8][128];
    __shared__ __align__(16) float Bs[8][128];
    const int tid = threadIdx.x;
    const int tx = tid & 15, ty = tid >> 4;
    const int row0 = blockIdx.y * 128, col0 = blockIdx.x * 128;

    float acc[8][8];
#pragma unroll
    for (int i = 0; i < 8; i++)
#pragma unroll
        for (int j = 0; j < 8; j++) acc[i][j] = 0.f;

    const int aRow = tid >> 1, aCol = (tid & 1) * 4;
    const int bRow = tid >> 5, bCol = (tid & 31) * 4;

    for (int k0 = 0; k0 < Kd; k0 += 8) {
        float4 av;
        if (row0 + aRow < M)
            av = *(const float4*)(A + (size_t)(row0 + aRow) * Kd + k0 + aCol);
        else
            av = make_float4(0.f, 0.f, 0.f, 0.f);
        As[aCol + 0][aRow] = av.x; As[aCol + 1][aRow] = av.y;
        As[aCol + 2][aRow] = av.z; As[aCol + 3][aRow] = av.w;

        if (!TB) {
            float4 bv = *(const float4*)(B + (size_t)(k0 + bRow) * Nm + col0 + bCol);
            Bs[bRow][bCol + 0] = bv.x; Bs[bRow][bCol + 1] = bv.y;
            Bs[bRow][bCol + 2] = bv.z; Bs[bRow][bCol + 3] = bv.w;
        } else {
            // B stored [Nm, Kd]; need Bs[k][n] = B[col0+n][k0+k]
            const int nI = tid >> 1, k4 = (tid & 1) * 4;
            float4 bv = *(const float4*)(B + (size_t)(col0 + nI) * Kd + k0 + k4);
            Bs[k4 + 0][nI] = bv.x; Bs[k4 + 1][nI] = bv.y;
            Bs[k4 + 2][nI] = bv.z; Bs[k4 + 3][nI] = bv.w;
        }
        __syncthreads();

#pragma unroll
        for (int kk = 0; kk < 8; kk++) {
            float4 a0 = *(const float4*)&As[kk][ty * 8];
            float4 a1 = *(const float4*)&As[kk][ty * 8 + 4];
            float4 b0 = *(const float4*)&Bs[kk][tx * 8];
            float4 b1 = *(const float4*)&Bs[kk][tx * 8 + 4];
            float a[8] = {a0.x, a0.y, a0.z, a0.w, a1.x, a1.y, a1.z, a1.w};
            float b[8] = {b0.x, b0.y, b0.z, b0.w, b1.x, b1.y, b1.z, b1.w};
#pragma unroll
            for (int i = 0; i < 8; i++)
#pragma unroll
                for (int j = 0; j < 8; j++)
                    acc[i][j] = fmaf(a[i], b[j], acc[i][j]);
        }
        __syncthreads();
    }

#pragma unroll
    for (int i = 0; i < 8; i++) {
        int r = row0 + ty * 8 + i;
        if (r < M) {
#pragma unroll
            for (int j = 0; j < 8; j++) {
                int cI = col0 + tx * 8 + j;
                float v = acc[i][j];
                if (ACC)   v += Cm[(size_t)r * Nm + cI];
                if (BIAS_) v += bias[cI];
                if (RELU_) v = fmaxf(v, 0.f);
                Cm[(size_t)r * Nm + cI] = v;
            }
        }
    }
}

// ---------------- small kernels ----------------
__global__ void k_zero(float* p, int n) {
    int i = blockIdx.x * blockDim.x + threadIdx.x;
    if (i < n) p[i] = 0.f;
}

__global__ void k_deg(const int* __restrict__ dst) {
    int e = blockIdx.x * blockDim.x + threadIdx.x;
    if (e < NE) atomicAdd(&d_deg[dst[e]], 1.f);
}

__global__ void k_ew(const float* __restrict__ ea,
                     const float* __restrict__ mu,
                     const float* __restrict__ sg) {
    int e = blockIdx.x * blockDim.x + threadIdx.x;
    if (e >= NE) return;
    float a0 = ea[e * 2 + 0], a1 = ea[e * 2 + 1];
#pragma unroll
    for (int k = 0; k < KG; k++) {
        float dx = a0 - mu[k * 2 + 0];
        float dy = a1 - mu[k * 2 + 1];
        float s0 = sg[k * 2 + 0], s1 = sg[k * 2 + 1];
        float w = expf(-0.5f * (dx * dx / (1e-15f + s0 * s0) +
                                dy * dy / (1e-15f + s1 * s1)));
        d_ew[(size_t)e * KG + k] = w;
    }
}

// one warp per edge: msg[e,c] = sum_k w[e,k]*xg[src,k,c]; atomic into agg[dst]
__global__ void k_scatter(const int* __restrict__ src, const int* __restrict__ dst) {
    int wid  = (blockIdx.x * blockDim.x + threadIdx.x) >> 5;
    int lane = threadIdx.x & 31;
    if (wid >= NE) return;
    int s = src[wid], d = dst[wid];
    float wv = (lane < KG) ? d_ew[(size_t)wid * KG + lane] : 0.f;
    const float* xr = &d_xg[(size_t)s * (KG * C)];
    float a0 = 0.f, a1 = 0.f, a2 = 0.f, a3 = 0.f;
#pragma unroll
    for (int k = 0; k < KG; k++) {
        float wk = __shfl_sync(0xffffffffu, wv, k);
        a0 = fmaf(wk, xr[k * C + lane +  0], a0);
        a1 = fmaf(wk, xr[k * C + lane + 32], a1);
        a2 = fmaf(wk, xr[k * C + lane + 64], a2);
        a3 = fmaf(wk, xr[k * C + lane + 96], a3);
    }
    float* ag = &d_agg[(size_t)d * C];
    atomicAdd(ag + lane +  0, a0);
    atomicAdd(ag + lane + 32, a1);
    atomicAdd(ag + lane + 64, a2);
    atomicAdd(ag + lane + 96, a3);
}

__global__ void k_comb(const float* __restrict__ bias) {
    int i = blockIdx.x * blockDim.x + threadIdx.x;
    if (i >= NN * C) return;
    int n = i / C, c = i % C;
    d_h[i] = d_agg[i] / fmaxf(d_deg[n], 1.f) + d_hr[i] + bias[c];
}

__global__ void k_bnred() {  // <<<128,128>>>
    int c = threadIdx.x;
    float s = 0.f, q = 0.f;
    for (int r = blockIdx.x; r < NN; r += gridDim.x) {
        float v = d_h[(size_t)r * C + c];
        s += v; q += v * v;
    }
    atomicAdd(&d_bns[c], s);
    atomicAdd(&d_bnq[c], q);
}

__global__ void k_bnapp(const float* __restrict__ gamma,
                        const float* __restrict__ beta,
                        float* __restrict__ out_hl, int relu) {
    int i = blockIdx.x * blockDim.x + threadIdx.x;
    if (i >= NN * C) return;
    int c = i % C;
    float mean = d_bns[c] / (float)NN;
    float var  = d_bnq[c] / (float)NN - mean * mean;
    float v = (d_h[i] - mean) * rsqrtf(var + 1e-5f) * gamma[c] + beta[c];
    if (relu) v = fmaxf(v, 0.f);
    d_h[i] = v;
    out_hl[i] = v;
}

__device__ __forceinline__ float sigf(float x) { return 1.f / (1.f + expf(-x)); }

__global__ void k_cell(const float* __restrict__ bih, const float* __restrict__ bhh) {
    int i = blockIdx.x * blockDim.x + threadIdx.x;
    if (i >= NN * H) return;
    int n = i / H, j = i % H;
    const float* gr = &d_gates[(size_t)n * H4];
    float gi = gr[0 * H + j] + bih[0 * H + j] + bhh[0 * H + j];
    float gf = gr[1 * H + j] + bih[1 * H + j] + bhh[1 * H + j];
    float gg = gr[2 * H + j] + bih[2 * H + j] + bhh[2 * H + j];
    float go = gr[3 * H + j] + bih[3 * H + j] + bhh[3 * H + j];
    float cc = sigf(gf) * d_lc[i] + sigf(gi) * tanhf(gg);
    d_lc[i] = cc;
    d_lh[i] = sigf(go) * tanhf(cc);
}

// per-node dot(h, att_w_part) — one warp per node
__global__ void k_adot(const float* __restrict__ aw, float* __restrict__ out) {
    int wid  = (blockIdx.x * blockDim.x + threadIdx.x) >> 5;
    int lane = threadIdx.x & 31;
    if (wid >= NN) return;
    const float* hr = &d_lh[(size_t)wid * H];
    float s = 0.f;
#pragma unroll
    for (int j = lane; j < H; j += 32) s = fmaf(hr[j], aw[j], s);
#pragma unroll
    for (int o = 16; o > 0; o >>= 1) s += __shfl_down_sync(0xffffffffu, s, o);
    if (lane == 0) out[wid] = s;
}

// softmax over 5 layer-scores per node + weighted sum of h_list
__global__ void k_nrep(const float* __restrict__ x) {
    int n = blockIdx.x;
    int c = threadIdx.x;
    __shared__ float p[5];
    if (c == 0) {
        float a[5], m = -1e30f;
#pragma unroll
        for (int t = 0; t < 5; t++) {
            a[t] = d_af[t * NN + n] + d_ab[t * NN + n];
            m = fmaxf(m, a[t]);
        }
        float s = 0.f;
#pragma unroll
        for (int t = 0; t < 5; t++) { a[t] = expf(a[t] - m); s += a[t]; }
#pragma unroll
        for (int t = 0; t < 5; t++) p[t] = a[t] / s;
    }
    __syncthreads();
    float r = p[0] * x[(size_t)n * C + c];
#pragma unroll
    for (int t = 1; t < 5; t++) r = fmaf(p[t], d_hl[t - 1][(size_t)n * C + c], r);
    d_nrep[(size_t)n * C + c] = r;
}

__global__ void k_cnt(const int* __restrict__ batch) {
    int n = blockIdx.x * blockDim.x + threadIdx.x;
    if (n < NN) atomicAdd(&d_cnt[batch[n]], 1.f);
}

__global__ void k_pool(const int* __restrict__ batch) {
    int i = blockIdx.x * blockDim.x + threadIdx.x;
    if (i >= NN * C) return;
    int n = i / C, c = i % C;
    atomicAdd(&d_hg[(size_t)batch[n] * C + c], d_nrep[i]);
}

__global__ void k_pdiv() {
    int i = blockIdx.x * blockDim.x + threadIdx.x;
    if (i >= NB * C) return;
    d_hg[i] /= fmaxf(d_cnt[i / C], 1.f);
}

__global__ void k_ln(const float* __restrict__ g, const float* __restrict__ b,
                     float* __restrict__ out) {  // <<<NB, NOUT>>>
    int row = blockIdx.x, t = threadIdx.x;
    __shared__ float sm[NOUT];
    float v = d_z2[(size_t)row * NOUT + t];
    sm[t] = v;
    __syncthreads();
    for (int o = NOUT / 2; o > 0; o >>= 1) {
        if (t < o) sm[t] += sm[t + o];
        __syncthreads();
    }
    float mean = sm[0] / (float)NOUT;
    __syncthreads();
    float dv = v - mean;
    sm[t] = dv * dv;
    __syncthreads();
    for (int o = NOUT / 2; o > 0; o >>= 1) {
        if (t < o) sm[t] += sm[t + o];
        __syncthreads();
    }
    float var = sm[0] / (float)NOUT;
    out[(size_t)row * NOUT + t] = dv * rsqrtf(var + 1e-5f) * g[t] + b[t];
}

// ---------------- host ----------------
static float* symf(const void* s) {
    void* p = nullptr;
    cudaGetSymbolAddress(&p, s);
    return (float*)p;
}

extern "C" void kernel_launch(void* const* d_in, const int* in_sizes, int n_in,
                              void* d_out, int out_size) {
    const float* x     = (const float*)d_in[0];
    const int*   ei    = (const int*)d_in[1];
    const int*   src   = ei;
    const int*   dst   = ei + NE;
    const float* ea    = (const float*)d_in[2];
    const int*   batch = (const int*)d_in[3];
    const float* g     = (const float*)d_in[4];
    const float* root  = (const float*)d_in[5];
    const float* bias  = (const float*)d_in[6];
    const float* mu    = (const float*)d_in[7];
    const float* sigma = (const float*)d_in[8];
    const float* bng   = (const float*)d_in[9];
    const float* bnb   = (const float*)d_in[10];
    const float* wih   = (const float*)d_in[11];
    const float* whh   = (const float*)d_in[12];
    const float* bih   = (const float*)d_in[13];
    const float* bhh   = (const float*)d_in[14];
    const float* attw  = (const float*)d_in[15];
    const float* p1w   = (const float*)d_in[17];
    const float* p1b   = (const float*)d_in[18];
    const float* p2w   = (const float*)d_in[19];
    const float* p2b   = (const float*)d_in[20];
    const float* lng   = (const float*)d_in[21];
    const float* lnb   = (const float*)d_in[22];
    float* out = (float*)d_out;

    float* h     = symf(d_h);
    float* hl    = symf(d_hl);
    float* xg    = symf(d_xg);
    float* deg   = symf(d_deg);
    float* agg   = symf(d_agg);
    float* hr    = symf(d_hr);
    float* bns   = symf(d_bns);
    float* bnq   = symf(d_bnq);
    float* gates = symf(d_gates);
    float* lh    = symf(d_lh);
    float* lc    = symf(d_lc);
    float* af    = symf(d_af);
    float* ab    = symf(d_ab);
    float* cnt   = symf(d_cnt);
    float* hg    = symf(d_hg);
    float* z1    = symf(d_z1);
    float* z2    = symf(d_z2);

    const int TPB = 256;
    const dim3 blk(TPB);
    const int gridNC  = (NN * C + TPB - 1) / TPB;
    const int gridNH  = (NN * H + TPB - 1) / TPB;
    const int rowsN   = (NN + 127) / 128;

    // degree (fixed across layers)
    k_zero<<<(NN + TPB - 1) / TPB, blk>>>(deg, NN);
    k_deg<<<(NE + TPB - 1) / TPB, blk>>>(dst);

    // -------- GMMConv layers --------
    const float* hin = x;
    for (int i = 0; i < LL; i++) {
        // xg = h @ g[i]   [N,128]x[128,1024]
        sgemm<false, false, false, false>
            <<<dim3((KG * C) / 128, rowsN), blk>>>(hin, g + (size_t)i * C * KG * C,
                                                   xg, nullptr, NN, KG * C, C);
        k_ew<<<(NE + TPB - 1) / TPB, blk>>>(ea, mu + i * KG * 2, sigma + i * KG * 2);
        k_zero<<<gridNC, blk>>>(agg, NN * C);
        k_scatter<<<(NE * 32 + TPB - 1) / TPB, blk>>>(src, dst);
        // hr = h @ root[i]   [N,128]x[128,128]
        sgemm<false, false, false, false>
            <<<dim3(1, rowsN), blk>>>(hin, root + (size_t)i * C * C, hr, nullptr, NN, C, C);
        k_comb<<<gridNC, blk>>>(bias + i * C);
        // batchnorm (training stats)
        k_zero<<<1, C>>>(bns, C);
        k_zero<<<1, C>>>(bnq, C);
        k_bnred<<<128, 128>>>();
        k_bnapp<<<gridNC, blk>>>(bng + i * C, bnb + i * C, hl + (size_t)i * NN * C,
                                 (i < LL - 1) ? 1 : 0);
        hin = h;
    }

    // -------- bidirectional LSTM JumpingKnowledge --------
    for (int dir = 0; dir < 2; dir++) {
        k_zero<<<gridNH, blk>>>(lh, NN * H);
        k_zero<<<gridNH, blk>>>(lc, NN * H);
        float* aout = dir ? ab : af;
        for (int s = 0; s < 5; s++) {
            int t = dir ? (4 - s) : s;
            const float* xs = (t == 0) ? x : (hl + (size_t)(t - 1) * NN * C);
            // gates = xs @ w_ih^T   [N,128]x[1024,128]^T
            sgemm<true, false, false, false>
                <<<dim3(H4 / 128, rowsN), blk>>>(xs, wih + (size_t)dir * H4 * C,
                                                 gates, nullptr, NN, H4, C);
            if (s > 0) {
                // gates += lh @ w_hh^T   [N,256]x[1024,256]^T
                sgemm<true, true, false, false>
                    <<<dim3(H4 / 128, rowsN), blk>>>(lh, whh + (size_t)dir * H4 * H,
                                                     gates, nullptr, NN, H4, H);
            }
            k_cell<<<gridNH, blk>>>(bih + dir * H4, bhh + dir * H4);
            k_adot<<<(NN * 32 + TPB - 1) / TPB, blk>>>(attw + dir * H, aout + t * NN);
        }
    }

    // attention softmax + weighted node representation
    k_nrep<<<NN, C>>>(x);

    // global mean pool
    k_zero<<<(NB + TPB - 1) / TPB, blk>>>(cnt, NB);
    k_zero<<<(NB * C + TPB - 1) / TPB, blk>>>(hg, NB * C);
    k_cnt<<<(NN + TPB - 1) / TPB, blk>>>(batch);
    k_pool<<<gridNC, blk>>>(batch);
    k_pdiv<<<(NB * C + TPB - 1) / TPB, blk>>>();

    // MLP + LayerNorm
    sgemm<false, false, true, true>
        <<<dim3(NHID / 128, NB / 128), blk>>>(hg, p1w, z1, p1b, NB, NHID, C);
    sgemm<false, false, false, true>
        <<<dim3(NOUT / 128, NB / 128), blk>>>(z1, p2w, z2, p2b, NB, NOUT, NHID);
    k_ln<<<NB, NOUT>>>(lng, lnb, out);
}

// round 2
// speedup vs baseline: 2.1431x; 2.1431x over previous
#include <cuda_runtime.h>
#include <math.h>
#include <stdint.h>

// ---------------- problem constants ----------------
namespace {
constexpr int NN   = 30000;   // nodes
constexpr int NE   = 480000;  // edges
constexpr int C    = 128;     // channels (= F)
constexpr int KG   = 8;       // gaussians
constexpr int LL   = 4;       // layers
constexpr int H    = 256;     // LSTM hidden
constexpr int H4   = 1024;    // 4*H
constexpr int NHID = 512;
constexpr int NOUT = 256;
constexpr int NB   = 1024;    // graphs
}

// ---------------- scratch (device globals; no allocations allowed) -------
__device__ __align__(256) float d_h[NN * C];
__device__ __align__(256) float d_hl[LL][NN * C];
__device__ __align__(256) float d_xg[NN * KG * C];
__device__ __align__(256) float d_ew[NE * KG];
__device__ __align__(256) float d_deg[NN];
__device__ __align__(256) float d_agg[NN * C];
__device__ __align__(256) float d_hr[NN * C];
__device__ __align__(256) float d_bns[C];
__device__ __align__(256) float d_bnq[C];
__device__ __align__(256) float d_gates[NN * H4];
__device__ __align__(256) float d_lh[NN * H];
__device__ __align__(256) float d_lc[NN * H];
__device__ __align__(256) float d_af[5 * NN];
__device__ __align__(256) float d_ab[5 * NN];
__device__ __align__(256) float d_nrep[NN * C];
__device__ __align__(256) float d_cnt[NB];
__device__ __align__(256) float d_hg[NB * C];
__device__ __align__(256) float d_z1[NB * NHID];
__device__ __align__(256) float d_z2[NB * NOUT];

// ---------------- TF32 tensor-core GEMM ----------------
__device__ __forceinline__ uint32_t f2tf(float f) {
    uint32_t u;
    asm("cvt.rna.tf32.f32 %0, %1;" : "=r"(u) : "f"(f));
    return u;
}

__device__ __forceinline__ void mma8(float* c, const uint32_t* a, const uint32_t* b) {
    asm volatile(
        "mma.sync.aligned.m16n8k8.row.col.f32.tf32.tf32.f32 "
        "{%0,%1,%2,%3}, {%4,%5,%6,%7}, {%8,%9}, {%0,%1,%2,%3};"
        : "+f"(c[0]), "+f"(c[1]), "+f"(c[2]), "+f"(c[3])
        : "r"(a[0]), "r"(a[1]), "r"(a[2]), "r"(a[3]), "r"(b[0]), "r"(b[1]));
}

// C[M,N] = A[M,K] @ (TB ? B[N,K]^T : B[K,N]) (+ A2@B2^T if K2>0, TB only)
//          (+C if ACC) (+bias if BIAS) (relu if RELU)
// N % 128 == 0, K % 16 == 0. Block tile 128x128, BK=16, 256 threads.
// smem tiles stored row-major with stride 20 words -> conflict-free mma frag loads.
template <bool TB, bool ACC, bool RELU_, bool BIAS_>
__global__ __launch_bounds__(256) void tgemm(
    const float* __restrict__ A, const float* __restrict__ B,
    const float* __restrict__ A2, const float* __restrict__ B2,
    float* __restrict__ Cm, const float* __restrict__ bias,
    int M, int Nm, int Kd, int Kd2)
{
    __shared__ uint32_t As[128 * 20];   // [m][k] tf32
    __shared__ uint32_t Bs[128 * 20];   // [n][k] tf32

    const int tid  = threadIdx.x;
    const int lane = tid & 31;
    const int wid  = tid >> 5;
    const int wm   = wid & 3;          // 4 warps along M
    const int wn   = wid >> 2;         // 2 warps along N
    const int gid  = lane >> 2;        // 0..7
    const int tig  = lane & 3;         // 0..3
    const int row0 = blockIdx.y * 128, col0 = blockIdx.x * 128;

    float acc[2][8][4];
#pragma unroll
    for (int mi = 0; mi < 2; mi++)
#pragma unroll
        for (int ni = 0; ni < 8; ni++)
#pragma unroll
            for (int r = 0; r < 4; r++) acc[mi][ni][r] = 0.f;

    const int lr0 = tid >> 2, lc4 = (tid & 3) * 4;

    for (int seg = 0; seg < 2; seg++) {
        const float* Ap = seg ? A2 : A;
        const float* Bp = seg ? B2 : B;
        const int    Kc = seg ? Kd2 : Kd;
        if (Kc == 0) continue;

        for (int k0 = 0; k0 < Kc; k0 += 16) {
            // ---- load A tile (always [M,K] row-major) ----
#pragma unroll
            for (int rr = lr0; rr < 128; rr += 64) {
                int gr = row0 + rr;
                float4 v = make_float4(0.f, 0.f, 0.f, 0.f);
                if (gr < M)
                    v = *(const float4*)(Ap + (size_t)gr * Kc + k0 + lc4);
                uint32_t* s = &As[rr * 20 + lc4];
                s[0] = f2tf(v.x); s[1] = f2tf(v.y); s[2] = f2tf(v.z); s[3] = f2tf(v.w);
            }
            // ---- load B tile ----
            if (TB) {
#pragma unroll
                for (int rr = lr0; rr < 128; rr += 64) {
                    float4 v = *(const float4*)(Bp + (size_t)(col0 + rr) * Kc + k0 + lc4);
                    uint32_t* s = &Bs[rr * 20 + lc4];
                    s[0] = f2tf(v.x); s[1] = f2tf(v.y); s[2] = f2tf(v.z); s[3] = f2tf(v.w);
                }
            } else {
#pragma unroll
                for (int it = 0; it < 2; it++) {
                    int idx = tid + it * 256;
                    int nI = idx & 127, kq = (idx >> 7) * 4;
                    const float* bp = Bp + (size_t)(k0 + kq) * Nm + col0 + nI;
                    uint32_t* s = &Bs[nI * 20 + kq];
                    s[0] = f2tf(bp[0]);
                    s[1] = f2tf(bp[(size_t)Nm]);
                    s[2] = f2tf(bp[2 * (size_t)Nm]);
                    s[3] = f2tf(bp[3 * (size_t)Nm]);
                }
            }
            __syncthreads();

#pragma unroll
            for (int kk = 0; kk < 16; kk += 8) {
                uint32_t a[2][4], b[8][2];
#pragma unroll
                for (int mi = 0; mi < 2; mi++) {
                    int mr = wm * 32 + mi * 16;
                    a[mi][0] = As[(mr + gid)     * 20 + kk + tig];
                    a[mi][1] = As[(mr + gid + 8) * 20 + kk + tig];
                    a[mi][2] = As[(mr + gid)     * 20 + kk + tig + 4];
                    a[mi][3] = As[(mr + gid + 8) * 20 + kk + tig + 4];
                }
#pragma unroll
                for (int ni = 0; ni < 8; ni++) {
                    int nr = wn * 64 + ni * 8;
                    b[ni][0] = Bs[(nr + gid) * 20 + kk + tig];
                    b[ni][1] = Bs[(nr + gid) * 20 + kk + tig + 4];
                }
#pragma unroll
                for (int mi = 0; mi < 2; mi++)
#pragma unroll
                    for (int ni = 0; ni < 8; ni++)
                        mma8(acc[mi][ni], a[mi], b[ni]);
            }
            __syncthreads();
        }
    }

    // ---- epilogue ----
#pragma unroll
    for (int mi = 0; mi < 2; mi++) {
#pragma unroll
        for (int half = 0; half < 2; half++) {
            int r = row0 + wm * 32 + mi * 16 + gid + half * 8;
            if (r >= M) continue;
#pragma unroll
            for (int ni = 0; ni < 8; ni++) {
                int cI = col0 + wn * 64 + ni * 8 + tig * 2;
                float v0 = acc[mi][ni][half * 2 + 0];
                float v1 = acc[mi][ni][half * 2 + 1];
                float* cp = Cm + (size_t)r * Nm + cI;
                if (ACC)   { v0 += cp[0]; v1 += cp[1]; }
                if (BIAS_) { v0 += bias[cI]; v1 += bias[cI + 1]; }
                if (RELU_) { v0 = fmaxf(v0, 0.f); v1 = fmaxf(v1, 0.f); }
                cp[0] = v0; cp[1] = v1;
            }
        }
    }
}

// ---------------- small kernels ----------------
__global__ void k_zero(float* p, int n) {
    int i = blockIdx.x * blockDim.x + threadIdx.x;
    if (i < n) p[i] = 0.f;
}

__global__ void k_deg(const int* __restrict__ dst) {
    int e = blockIdx.x * blockDim.x + threadIdx.x;
    if (e < NE) atomicAdd(&d_deg[dst[e]], 1.f);
}

__global__ void k_ew(const float* __restrict__ ea,
                     const float* __restrict__ mu,
                     const float* __restrict__ sg) {
    int e = blockIdx.x * blockDim.x + threadIdx.x;
    if (e >= NE) return;
    float a0 = ea[e * 2 + 0], a1 = ea[e * 2 + 1];
#pragma unroll
    for (int k = 0; k < KG; k++) {
        float dx = a0 - mu[k * 2 + 0];
        float dy = a1 - mu[k * 2 + 1];
        float s0 = sg[k * 2 + 0], s1 = sg[k * 2 + 1];
        float w = expf(-0.5f * (dx * dx / (1e-15f + s0 * s0) +
                                dy * dy / (1e-15f + s1 * s1)));
        d_ew[(size_t)e * KG + k] = w;
    }
}

// one warp per edge: msg[e,c] = sum_k w[e,k]*xg[src,k,c]; atomic into agg[dst]
__global__ void k_scatter(const int* __restrict__ src, const int* __restrict__ dst) {
    int wid  = (blockIdx.x * blockDim.x + threadIdx.x) >> 5;
    int lane = threadIdx.x & 31;
    if (wid >= NE) return;
    int s = src[wid], d = dst[wid];
    float wv = (lane < KG) ? d_ew[(size_t)wid * KG + lane] : 0.f;
    const float* xr = &d_xg[(size_t)s * (KG * C)];
    float a0 = 0.f, a1 = 0.f, a2 = 0.f, a3 = 0.f;
#pragma unroll
    for (int k = 0; k < KG; k++) {
        float wk = __shfl_sync(0xffffffffu, wv, k);
        a0 = fmaf(wk, xr[k * C + lane +  0], a0);
        a1 = fmaf(wk, xr[k * C + lane + 32], a1);
        a2 = fmaf(wk, xr[k * C + lane + 64], a2);
        a3 = fmaf(wk, xr[k * C + lane + 96], a3);
    }
    float* ag = &d_agg[(size_t)d * C];
    atomicAdd(ag + lane +  0, a0);
    atomicAdd(ag + lane + 32, a1);
    atomicAdd(ag + lane + 64, a2);
    atomicAdd(ag + lane + 96, a3);
}

__global__ void k_comb(const float* __restrict__ bias) {
    int i = blockIdx.x * blockDim.x + threadIdx.x;
    if (i >= NN * C) return;
    int n = i / C, c = i % C;
    d_h[i] = d_agg[i] / fmaxf(d_deg[n], 1.f) + d_hr[i] + bias[c];
}

__global__ void k_bnred() {  // <<<128,128>>>
    int c = threadIdx.x;
    float s = 0.f, q = 0.f;
    for (int r = blockIdx.x; r < NN; r += gridDim.x) {
        float v = d_h[(size_t)r * C + c];
        s += v; q += v * v;
    }
    atomicAdd(&d_bns[c], s);
    atomicAdd(&d_bnq[c], q);
}

__global__ void k_bnapp(const float* __restrict__ gamma,
                        const float* __restrict__ beta,
                        float* __restrict__ out_hl, int relu) {
    int i = blockIdx.x * blockDim.x + threadIdx.x;
    if (i >= NN * C) return;
    int c = i % C;
    float mean = d_bns[c] / (float)NN;
    float var  = d_bnq[c] / (float)NN - mean * mean;
    float v = (d_h[i] - mean) * rsqrtf(var + 1e-5f) * gamma[c] + beta[c];
    if (relu) v = fmaxf(v, 0.f);
    d_h[i] = v;
    out_hl[i] = v;
}

__device__ __forceinline__ float sigf(float x) { return 1.f / (1.f + expf(-x)); }

// fused LSTM cell + attention dot: one block (H threads) per node
__global__ __launch_bounds__(H) void k_cellf(const float* __restrict__ bih,
                                             const float* __restrict__ bhh,
                                             const float* __restrict__ aw,
                                             float* __restrict__ aout) {
    int n = blockIdx.x, j = threadIdx.x;
    const float* gr = &d_gates[(size_t)n * H4];
    float gi = gr[0 * H + j] + bih[0 * H + j] + bhh[0 * H + j];
    float gf = gr[1 * H + j] + bih[1 * H + j] + bhh[1 * H + j];
    float gg = gr[2 * H + j] + bih[2 * H + j] + bhh[2 * H + j];
    float go = gr[3 * H + j] + bih[3 * H + j] + bhh[3 * H + j];
    size_t i = (size_t)n * H + j;
    float cc = sigf(gf) * d_lc[i] + sigf(gi) * tanhf(gg);
    d_lc[i] = cc;
    float hh = sigf(go) * tanhf(cc);
    d_lh[i] = hh;

    __shared__ float sm[H];
    sm[j] = hh * aw[j];
    __syncthreads();
#pragma unroll
    for (int o = H / 2; o >= 32; o >>= 1) {
        if (j < o) sm[j] += sm[j + o];
        __syncthreads();
    }
    if (j < 32) {
        float s = sm[j];
#pragma unroll
        for (int o = 16; o > 0; o >>= 1) s += __shfl_down_sync(0xffffffffu, s, o);
        if (j == 0) aout[n] = s;
    }
}

// softmax over 5 layer-scores per node + weighted sum of h_list
__global__ void k_nrep(const float* __restrict__ x) {
    int n = blockIdx.x;
    int c = threadIdx.x;
    __shared__ float p[5];
    if (c == 0) {
        float a[5], m = -1e30f;
#pragma unroll
        for (int t = 0; t < 5; t++) {
            a[t] = d_af[t * NN + n] + d_ab[t * NN + n];
            m = fmaxf(m, a[t]);
        }
        float s = 0.f;
#pragma unroll
        for (int t = 0; t < 5; t++) { a[t] = expf(a[t] - m); s += a[t]; }
#pragma unroll
        for (int t = 0; t < 5; t++) p[t] = a[t] / s;
    }
    __syncthreads();
    float r = p[0] * x[(size_t)n * C + c];
#pragma unroll
    for (int t = 1; t < 5; t++) r = fmaf(p[t], d_hl[t - 1][(size_t)n * C + c], r);
    d_nrep[(size_t)n * C + c] = r;
}

__global__ void k_cnt(const int* __restrict__ batch) {
    int n = blockIdx.x * blockDim.x + threadIdx.x;
    if (n < NN) atomicAdd(&d_cnt[batch[n]], 1.f);
}

__global__ void k_pool(const int* __restrict__ batch) {
    int i = blockIdx.x * blockDim.x + threadIdx.x;
    if (i >= NN * C) return;
    int n = i / C, c = i % C;
    atomicAdd(&d_hg[(size_t)batch[n] * C + c], d_nrep[i]);
}

__global__ void k_pdiv() {
    int i = blockIdx.x * blockDim.x + threadIdx.x;
    if (i >= NB * C) return;
    d_hg[i] /= fmaxf(d_cnt[i / C], 1.f);
}

__global__ void k_ln(const float* __restrict__ g, const float* __restrict__ b,
                     float* __restrict__ out) {  // <<<NB, NOUT>>>
    int row = blockIdx.x, t = threadIdx.x;
    __shared__ float sm[NOUT];
    float v = d_z2[(size_t)row * NOUT + t];
    sm[t] = v;
    __syncthreads();
    for (int o = NOUT / 2; o > 0; o >>= 1) {
        if (t < o) sm[t] += sm[t + o];
        __syncthreads();
    }
    float mean = sm[0] / (float)NOUT;
    __syncthreads();
    float dv = v - mean;
    sm[t] = dv * dv;
    __syncthreads();
    for (int o = NOUT / 2; o > 0; o >>= 1) {
        if (t < o) sm[t] += sm[t + o];
        __syncthreads();
    }
    float var = sm[0] / (float)NOUT;
    out[(size_t)row * NOUT + t] = dv * rsqrtf(var + 1e-5f) * g[t] + b[t];
}

// ---------------- host ----------------
static float* symf(const void* s) {
    void* p = nullptr;
    cudaGetSymbolAddress(&p, s);
    return (float*)p;
}

extern "C" void kernel_launch(void* const* d_in, const int* in_sizes, int n_in,
                              void* d_out, int out_size) {
    const float* x     = (const float*)d_in[0];
    const int*   ei    = (const int*)d_in[1];
    const int*   src   = ei;
    const int*   dst   = ei + NE;
    const float* ea    = (const float*)d_in[2];
    const int*   batch = (const int*)d_in[3];
    const float* g     = (const float*)d_in[4];
    const float* root  = (const float*)d_in[5];
    const float* bias  = (const float*)d_in[6];
    const float* mu    = (const float*)d_in[7];
    const float* sigma = (const float*)d_in[8];
    const float* bng   = (const float*)d_in[9];
    const float* bnb   = (const float*)d_in[10];
    const float* wih   = (const float*)d_in[11];
    const float* whh   = (const float*)d_in[12];
    const float* bih   = (const float*)d_in[13];
    const float* bhh   = (const float*)d_in[14];
    const float* attw  = (const float*)d_in[15];
    const float* p1w   = (const float*)d_in[17];
    const float* p1b   = (const float*)d_in[18];
    const float* p2w   = (const float*)d_in[19];
    const float* p2b   = (const float*)d_in[20];
    const float* lng   = (const float*)d_in[21];
    const float* lnb   = (const float*)d_in[22];
    float* out = (float*)d_out;

    float* h     = symf(d_h);
    float* hl    = symf(d_hl);
    float* xg    = symf(d_xg);
    float* deg   = symf(d_deg);
    float* agg   = symf(d_agg);
    float* hr    = symf(d_hr);
    float* bns   = symf(d_bns);
    float* bnq   = symf(d_bnq);
    float* gates = symf(d_gates);
    float* lh    = symf(d_lh);
    float* lc    = symf(d_lc);
    float* af    = symf(d_af);
    float* ab    = symf(d_ab);
    float* cnt   = symf(d_cnt);
    float* hg    = symf(d_hg);
    float* z1    = symf(d_z1);
    float* z2    = symf(d_z2);

    const int TPB = 256;
    const dim3 blk(TPB);
    const int gridNC = (NN * C + TPB - 1) / TPB;
    const int gridNH = (NN * H + TPB - 1) / TPB;
    const int rowsN  = (NN + 127) / 128;

    // degree (fixed across layers)
    k_zero<<<(NN + TPB - 1) / TPB, blk>>>(deg, NN);
    k_deg<<<(NE + TPB - 1) / TPB, blk>>>(dst);

    // -------- GMMConv layers --------
    const float* hin = x;
    for (int i = 0; i < LL; i++) {
        // xg = h @ g[i]   [N,128]x[128,1024]
        tgemm<false, false, false, false>
            <<<dim3((KG * C) / 128, rowsN), blk>>>(hin, g + (size_t)i * C * KG * C,
                                                   nullptr, nullptr, xg, nullptr,
                                                   NN, KG * C, C, 0);
        k_ew<<<(NE + TPB - 1) / TPB, blk>>>(ea, mu + i * KG * 2, sigma + i * KG * 2);
        k_zero<<<gridNC, blk>>>(agg, NN * C);
        k_scatter<<<(NE * 32 + TPB - 1) / TPB, blk>>>(src, dst);
        // hr = h @ root[i]   [N,128]x[128,128]
        tgemm<false, false, false, false>
            <<<dim3(1, rowsN), blk>>>(hin, root + (size_t)i * C * C,
                                      nullptr, nullptr, hr, nullptr, NN, C, C, 0);
        k_comb<<<gridNC, blk>>>(bias + i * C);
        // batchnorm (training stats)
        k_zero<<<1, C>>>(bns, C);
        k_zero<<<1, C>>>(bnq, C);
        k_bnred<<<128, 128>>>();
        k_bnapp<<<gridNC, blk>>>(bng + i * C, bnb + i * C, hl + (size_t)i * NN * C,
                                 (i < LL - 1) ? 1 : 0);
        hin = h;
    }

    // -------- bidirectional LSTM JumpingKnowledge --------
    for (int dir = 0; dir < 2; dir++) {
        k_zero<<<gridNH, blk>>>(lc, NN * H);
        float* aout = dir ? ab : af;
        for (int s = 0; s < 5; s++) {
            int t = dir ? (4 - s) : s;
            const float* xs = (t == 0) ? x : (hl + (size_t)(t - 1) * NN * C);
            // gates = xs @ w_ih^T (+ lh @ w_hh^T when s>0) — single dual-K GEMM
            tgemm<true, false, false, false>
                <<<dim3(H4 / 128, rowsN), blk>>>(
                    xs, wih + (size_t)dir * H4 * C,
                    lh, whh + (size_t)dir * H4 * H,
                    gates, nullptr, NN, H4, C, (s > 0) ? H : 0);
            k_cellf<<<NN, H>>>(bih + dir * H4, bhh + dir * H4,
                               attw + dir * H, aout + t * NN);
        }
    }

    // attention softmax + weighted node representation
    k_nrep<<<NN, C>>>(x);

    // global mean pool
    k_zero<<<(NB + TPB - 1) / TPB, blk>>>(cnt, NB);
    k_zero<<<(NB * C + TPB - 1) / TPB, blk>>>(hg, NB * C);
    k_cnt<<<(NN + TPB - 1) / TPB, blk>>>(batch);
    k_pool<<<gridNC, blk>>>(batch);
    k_pdiv<<<(NB * C + TPB - 1) / TPB, blk>>>();

    // MLP + LayerNorm
    tgemm<false, false, true, true>
        <<<dim3(NHID / 128, NB / 128), blk>>>(hg, p1w, nullptr, nullptr,
                                              z1, p1b, NB, NHID, C, 0);
    tgemm<false, false, false, true>
        <<<dim3(NOUT / 128, NB / 128), blk>>>(z1, p2w, nullptr, nullptr,
                                              z2, p2b, NB, NOUT, NHID, 0);
    k_ln<<<NB, NOUT>>>(lng, lnb, out);
}

// round 3
// speedup vs baseline: 2.3329x; 1.0885x over previous
#include <cuda_runtime.h>
#include <math.h>
#include <stdint.h>

// ---------------- problem constants ----------------
namespace {
constexpr int NN   = 30000;   // nodes
constexpr int NE   = 480000;  // edges
constexpr int C    = 128;     // channels (= F)
constexpr int KG   = 8;       // gaussians
constexpr int LL   = 4;       // layers
constexpr int H    = 256;     // LSTM hidden
constexpr int H4   = 1024;    // 4*H
constexpr int NHID = 512;
constexpr int NOUT = 256;
constexpr int NB   = 1024;    // graphs
}

// ---------------- scratch (device globals; no allocations allowed) -------
__device__ __align__(256) float d_h[NN * C];
__device__ __align__(256) float d_hl[LL][NN * C];
__device__ __align__(256) float d_xg[NN * KG * C];
__device__ __align__(256) float d_ew[NE * KG];
__device__ __align__(256) float d_deg[NN];
__device__ __align__(256) float d_agg[NN * C];
__device__ __align__(256) float d_hr[NN * C];
__device__ __align__(256) float d_bns[C];
__device__ __align__(256) float d_bnq[C];
__device__ __align__(256) float d_gates[2][NN * H4];
__device__ __align__(256) float d_lh[2][NN * H];
__device__ __align__(256) float d_lc[2][NN * H];
__device__ __align__(256) float d_af[5 * NN];
__device__ __align__(256) float d_ab[5 * NN];
__device__ __align__(256) float d_nrep[NN * C];
__device__ __align__(256) float d_cnt[NB];
__device__ __align__(256) float d_hg[NB * C];
__device__ __align__(256) float d_z1[NB * NHID];
__device__ __align__(256) float d_z2[NB * NOUT];

// ---------------- TF32 tensor-core GEMM (cp.async 2-stage) ----------------
__device__ __forceinline__ uint32_t f2tf(float f) {
    uint32_t u;
    asm("cvt.rna.tf32.f32 %0, %1;" : "=r"(u) : "f"(f));
    return u;
}
__device__ __forceinline__ uint32_t tfw(uint32_t rawbits) {
    return f2tf(__uint_as_float(rawbits));
}

__device__ __forceinline__ void mma8(float* c, const uint32_t* a, const uint32_t* b) {
    asm volatile(
        "mma.sync.aligned.m16n8k8.row.col.f32.tf32.tf32.f32 "
        "{%0,%1,%2,%3}, {%4,%5,%6,%7}, {%8,%9}, {%0,%1,%2,%3};"
        : "+f"(c[0]), "+f"(c[1]), "+f"(c[2]), "+f"(c[3])
        : "r"(a[0]), "r"(a[1]), "r"(a[2]), "r"(a[3]), "r"(b[0]), "r"(b[1]));
}

__device__ __forceinline__ void cpa16(uint32_t sdst, const void* gsrc, int srcsz) {
    asm volatile("cp.async.ca.shared.global [%0], [%1], 16, %2;\n"
                 :: "r"(sdst), "l"(gsrc), "r"(srcsz));
}
__device__ __forceinline__ void cpa_commit() {
    asm volatile("cp.async.commit_group;\n");
}
__device__ __forceinline__ void cpa_wait1() {
    asm volatile("cp.async.wait_group 1;\n");
}

struct GA {
    const float* A;   // [M, Kd]
    const float* B;   // TB: [Nm, Kd]  else [Kd, Nm]
    const float* A2;  // [M, Kd2] (TB only)
    const float* B2;  // [Nm, Kd2]
    float* Cm;        // [M, Nm]
};

// C = A@B(^T) (+ A2@B2^T if Kd2>0, TB only) (+C if ACC)(+bias)(relu)
// Nm%128==0, Kd,Kd2 %16==0. 128x128 tile, BK=16, 256 thr, blockIdx.z picks GA.
template <bool TB, bool ACC, bool RELU_, bool BIAS_>
__global__ __launch_bounds__(256) void tgemm(
    GA g0, GA g1, const float* __restrict__ bias, int M, int Nm, int Kd, int Kd2)
{
    __shared__ uint32_t As[2][128 * 20];   // [m][k] fp32 bits
    __shared__ uint32_t Bs[2][2560];       // TB: [n][k] stride20 ; !TB: [k][n] stride136

    const GA ga = blockIdx.z ? g1 : g0;
    const float* __restrict__ A  = ga.A;
    const float* __restrict__ B  = ga.B;
    const float* __restrict__ A2 = ga.A2;
    const float* __restrict__ B2 = ga.B2;
    float* __restrict__ Cm = ga.Cm;

    const int tid  = threadIdx.x;
    const int lane = tid & 31;
    const int wid  = tid >> 5;
    const int wm   = wid & 3;
    const int wn   = wid >> 2;
    const int gid  = lane >> 2;
    const int tig  = lane & 3;
    const int row0 = blockIdx.y * 128, col0 = blockIdx.x * 128;

    const int nt1 = Kd >> 4;
    const int nt  = nt1 + (Kd2 >> 4);

    float acc[2][8][4];
#pragma unroll
    for (int mi = 0; mi < 2; mi++)
#pragma unroll
        for (int ni = 0; ni < 8; ni++)
#pragma unroll
            for (int r = 0; r < 4; r++) acc[mi][ni][r] = 0.f;

    const int lr0 = tid >> 2, lc4 = (tid & 3) * 4;   // A/B(TB) loader coords

    auto loadTile = [&](int t, int st) {
        const float* Ap; const float* Bp; int Kc, k0;
        if (t < nt1) { Ap = A;  Bp = B;  Kc = Kd;  k0 = t << 4; }
        else         { Ap = A2; Bp = B2; Kc = Kd2; k0 = (t - nt1) << 4; }
        // A tile: [m][k] stride 20
#pragma unroll
        for (int it = 0; it < 2; it++) {
            int rr = lr0 + it * 64;
            int gr = row0 + rr;
            uint32_t dst = (uint32_t)__cvta_generic_to_shared(&As[st][rr * 20 + lc4]);
            cpa16(dst, Ap + (size_t)gr * Kc + k0 + lc4, gr < M ? 16 : 0);
        }
        if (TB) {
#pragma unroll
            for (int it = 0; it < 2; it++) {
                int rr = lr0 + it * 64;
                uint32_t dst = (uint32_t)__cvta_generic_to_shared(&Bs[st][rr * 20 + lc4]);
                cpa16(dst, Bp + (size_t)(col0 + rr) * Kc + k0 + lc4, 16);
            }
        } else {
#pragma unroll
            for (int it = 0; it < 2; it++) {
                int idx = tid + it * 256;
                int kk = idx >> 5, n4 = (idx & 31) * 4;
                uint32_t dst = (uint32_t)__cvta_generic_to_shared(&Bs[st][kk * 136 + n4]);
                cpa16(dst, Bp + (size_t)(k0 + kk) * Nm + col0 + n4, 16);
            }
        }
    };

    loadTile(0, 0);
    cpa_commit();

    for (int t = 0; t < nt; t++) {
        if (t + 1 < nt) loadTile(t + 1, (t + 1) & 1);
        cpa_commit();
        cpa_wait1();
        __syncthreads();

        const int st = t & 1;
#pragma unroll
        for (int kk = 0; kk < 16; kk += 8) {
            uint32_t a[2][4], b[8][2];
#pragma unroll
            for (int mi = 0; mi < 2; mi++) {
                int mr = wm * 32 + mi * 16;
                a[mi][0] = tfw(As[st][(mr + gid)     * 20 + kk + tig]);
                a[mi][1] = tfw(As[st][(mr + gid + 8) * 20 + kk + tig]);
                a[mi][2] = tfw(As[st][(mr + gid)     * 20 + kk + tig + 4]);
                a[mi][3] = tfw(As[st][(mr + gid + 8) * 20 + kk + tig + 4]);
            }
#pragma unroll
            for (int ni = 0; ni < 8; ni++) {
                int nr = wn * 64 + ni * 8;
                if (TB) {
                    b[ni][0] = tfw(Bs[st][(nr + gid) * 20 + kk + tig]);
                    b[ni][1] = tfw(Bs[st][(nr + gid) * 20 + kk + tig + 4]);
                } else {
                    b[ni][0] = tfw(Bs[st][(kk + tig)     * 136 + nr + gid]);
                    b[ni][1] = tfw(Bs[st][(kk + tig + 4) * 136 + nr + gid]);
                }
            }
#pragma unroll
            for (int mi = 0; mi < 2; mi++)
#pragma unroll
                for (int ni = 0; ni < 8; ni++)
                    mma8(acc[mi][ni], a[mi], b[ni]);
        }
        __syncthreads();
    }

    // ---- epilogue ----
#pragma unroll
    for (int mi = 0; mi < 2; mi++) {
#pragma unroll
        for (int half = 0; half < 2; half++) {
            int r = row0 + wm * 32 + mi * 16 + gid + half * 8;
            if (r >= M) continue;
#pragma unroll
            for (int ni = 0; ni < 8; ni++) {
                int cI = col0 + wn * 64 + ni * 8 + tig * 2;
                float v0 = acc[mi][ni][half * 2 + 0];
                float v1 = acc[mi][ni][half * 2 + 1];
                float* cp = Cm + (size_t)r * Nm + cI;
                if (ACC)   { v0 += cp[0]; v1 += cp[1]; }
                if (BIAS_) { v0 += bias[cI]; v1 += bias[cI + 1]; }
                if (RELU_) { v0 = fmaxf(v0, 0.f); v1 = fmaxf(v1, 0.f); }
                cp[0] = v0; cp[1] = v1;
            }
        }
    }
}

// ---------------- small kernels ----------------
__global__ void k_zero(float* p, int n) {
    int i = blockIdx.x * blockDim.x + threadIdx.x;
    if (i < n) p[i] = 0.f;
}

__global__ void k_deg(const int* __restrict__ dst) {
    int e = blockIdx.x * blockDim.x + threadIdx.x;
    if (e < NE) atomicAdd(&d_deg[dst[e]], 1.f);
}

__global__ void k_ew(const float* __restrict__ ea,
                     const float* __restrict__ mu,
                     const float* __restrict__ sg) {
    int e = blockIdx.x * blockDim.x + threadIdx.x;
    if (e >= NE) return;
    float a0 = ea[e * 2 + 0], a1 = ea[e * 2 + 1];
#pragma unroll
    for (int k = 0; k < KG; k++) {
        float dx = a0 - mu[k * 2 + 0];
        float dy = a1 - mu[k * 2 + 1];
        float s0 = sg[k * 2 + 0], s1 = sg[k * 2 + 1];
        float w = expf(-0.5f * (dx * dx / (1e-15f + s0 * s0) +
                                dy * dy / (1e-15f + s1 * s1)));
        d_ew[(size_t)e * KG + k] = w;
    }
}

// one warp per edge: msg[e,c] = sum_k w[e,k]*xg[src,k,c]; atomic into agg[dst]
__global__ void k_scatter(const int* __restrict__ src, const int* __restrict__ dst) {
    int wid  = (blockIdx.x * blockDim.x + threadIdx.x) >> 5;
    int lane = threadIdx.x & 31;
    if (wid >= NE) return;
    int s = src[wid], d = dst[wid];
    float wv = (lane < KG) ? d_ew[(size_t)wid * KG + lane] : 0.f;
    const float* xr = &d_xg[(size_t)s * (KG * C)];
    float a0 = 0.f, a1 = 0.f, a2 = 0.f, a3 = 0.f;
#pragma unroll
    for (int k = 0; k < KG; k++) {
        float wk = __shfl_sync(0xffffffffu, wv, k);
        a0 = fmaf(wk, xr[k * C + lane +  0], a0);
        a1 = fmaf(wk, xr[k * C + lane + 32], a1);
        a2 = fmaf(wk, xr[k * C + lane + 64], a2);
        a3 = fmaf(wk, xr[k * C + lane + 96], a3);
    }
    float* ag = &d_agg[(size_t)d * C];
    atomicAdd(ag + lane +  0, a0);
    atomicAdd(ag + lane + 32, a1);
    atomicAdd(ag + lane + 64, a2);
    atomicAdd(ag + lane + 96, a3);
}

__global__ void k_comb(const float* __restrict__ bias) {
    int i = blockIdx.x * blockDim.x + threadIdx.x;
    if (i >= NN * C) return;
    int n = i / C, c = i % C;
    d_h[i] = d_agg[i] / fmaxf(d_deg[n], 1.f) + d_hr[i] + bias[c];
}

__global__ void k_bnred() {  // <<<128,128>>>
    int c = threadIdx.x;
    float s = 0.f, q = 0.f;
    for (int r = blockIdx.x; r < NN; r += gridDim.x) {
        float v = d_h[(size_t)r * C + c];
        s += v; q += v * v;
    }
    atomicAdd(&d_bns[c], s);
    atomicAdd(&d_bnq[c], q);
}

__global__ void k_bnapp(const float* __restrict__ gamma,
                        const float* __restrict__ beta,
                        float* __restrict__ out_hl, int relu) {
    int i = blockIdx.x * blockDim.x + threadIdx.x;
    if (i >= NN * C) return;
    int c = i % C;
    float mean = d_bns[c] / (float)NN;
    float var  = d_bnq[c] / (float)NN - mean * mean;
    float v = (d_h[i] - mean) * rsqrtf(var + 1e-5f) * gamma[c] + beta[c];
    if (relu) v = fmaxf(v, 0.f);
    d_h[i] = v;
    out_hl[i] = v;
}

__device__ __forceinline__ float sigf(float x) { return 1.f / (1.f + expf(-x)); }

// fused LSTM cell + attention dot, both directions: grid (NN, 2), block H
__global__ __launch_bounds__(H) void k_cellf(const float* __restrict__ bih,
                                             const float* __restrict__ bhh,
                                             const float* __restrict__ attw,
                                             int s) {
    int n = blockIdx.x, dir = blockIdx.y, j = threadIdx.x;
    const float* gr = &d_gates[dir][(size_t)n * H4];
    const float* bi = bih + dir * H4;
    const float* bh = bhh + dir * H4;
    float gi = gr[0 * H + j] + bi[0 * H + j] + bh[0 * H + j];
    float gf = gr[1 * H + j] + bi[1 * H + j] + bh[1 * H + j];
    float gg = gr[2 * H + j] + bi[2 * H + j] + bh[2 * H + j];
    float go = gr[3 * H + j] + bi[3 * H + j] + bh[3 * H + j];
    size_t i = (size_t)n * H + j;
    float cc = sigf(gf) * d_lc[dir][i] + sigf(gi) * tanhf(gg);
    d_lc[dir][i] = cc;
    float hh = sigf(go) * tanhf(cc);
    d_lh[dir][i] = hh;

    __shared__ float sm[H];
    sm[j] = hh * attw[dir * H + j];
    __syncthreads();
#pragma unroll
    for (int o = H / 2; o >= 32; o >>= 1) {
        if (j < o) sm[j] += sm[j + o];
        __syncthreads();
    }
    if (j < 32) {
        float v = sm[j];
#pragma unroll
        for (int o = 16; o > 0; o >>= 1) v += __shfl_down_sync(0xffffffffu, v, o);
        if (j == 0) {
            int t = dir ? (4 - s) : s;
            float* aout = dir ? d_ab : d_af;
            aout[t * NN + n] = v;
        }
    }
}

// softmax over 5 layer-scores per node + weighted sum of h_list
__global__ void k_nrep(const float* __restrict__ x) {
    int n = blockIdx.x;
    int c = threadIdx.x;
    __shared__ float p[5];
    if (c == 0) {
        float a[5], m = -1e30f;
#pragma unroll
        for (int t = 0; t < 5; t++) {
            a[t] = d_af[t * NN + n] + d_ab[t * NN + n];
            m = fmaxf(m, a[t]);
        }
        float s = 0.f;
#pragma unroll
        for (int t = 0; t < 5; t++) { a[t] = expf(a[t] - m); s += a[t]; }
#pragma unroll
        for (int t = 0; t < 5; t++) p[t] = a[t] / s;
    }
    __syncthreads();
    float r = p[0] * x[(size_t)n * C + c];
#pragma unroll
    for (int t = 1; t < 5; t++) r = fmaf(p[t], d_hl[t - 1][(size_t)n * C + c], r);
    d_nrep[(size_t)n * C + c] = r;
}

__global__ void k_cnt(const int* __restrict__ batch) {
    int n = blockIdx.x * blockDim.x + threadIdx.x;
    if (n < NN) atomicAdd(&d_cnt[batch[n]], 1.f);
}

__global__ void k_pool(const int* __restrict__ batch) {
    int i = blockIdx.x * blockDim.x + threadIdx.x;
    if (i >= NN * C) return;
    int n = i / C, c = i % C;
    atomicAdd(&d_hg[(size_t)batch[n] * C + c], d_nrep[i]);
}

__global__ void k_pdiv() {
    int i = blockIdx.x * blockDim.x + threadIdx.x;
    if (i >= NB * C) return;
    d_hg[i] /= fmaxf(d_cnt[i / C], 1.f);
}

__global__ void k_ln(const float* __restrict__ g, const float* __restrict__ b,
                     float* __restrict__ out) {  // <<<NB, NOUT>>>
    int row = blockIdx.x, t = threadIdx.x;
    __shared__ float sm[NOUT];
    float v = d_z2[(size_t)row * NOUT + t];
    sm[t] = v;
    __syncthreads();
    for (int o = NOUT / 2; o > 0; o >>= 1) {
        if (t < o) sm[t] += sm[t + o];
        __syncthreads();
    }
    float mean = sm[0] / (float)NOUT;
    __syncthreads();
    float dv = v - mean;
    sm[t] = dv * dv;
    __syncthreads();
    for (int o = NOUT / 2; o > 0; o >>= 1) {
        if (t < o) sm[t] += sm[t + o];
        __syncthreads();
    }
    float var = sm[0] / (float)NOUT;
    out[(size_t)row * NOUT + t] = dv * rsqrtf(var + 1e-5f) * g[t] + b[t];
}

// ---------------- host ----------------
static float* symf(const void* s) {
    void* p = nullptr;
    cudaGetSymbolAddress(&p, s);
    return (float*)p;
}

extern "C" void kernel_launch(void* const* d_in, const int* in_sizes, int n_in,
                              void* d_out, int out_size) {
    const float* x     = (const float*)d_in[0];
    const int*   ei    = (const int*)d_in[1];
    const int*   src   = ei;
    const int*   dst   = ei + NE;
    const float* ea    = (const float*)d_in[2];
    const int*   batch = (const int*)d_in[3];
    const float* g     = (const float*)d_in[4];
    const float* root  = (const float*)d_in[5];
    const float* bias  = (const float*)d_in[6];
    const float* mu    = (const float*)d_in[7];
    const float* sigma = (const float*)d_in[8];
    const float* bng   = (const float*)d_in[9];
    const float* bnb   = (const float*)d_in[10];
    const float* wih   = (const float*)d_in[11];
    const float* whh   = (const float*)d_in[12];
    const float* bih   = (const float*)d_in[13];
    const float* bhh   = (const float*)d_in[14];
    const float* attw  = (const float*)d_in[15];
    const float* p1w   = (const float*)d_in[17];
    const float* p1b   = (const float*)d_in[18];
    const float* p2w   = (const float*)d_in[19];
    const float* p2b   = (const float*)d_in[20];
    const float* lng   = (const float*)d_in[21];
    const float* lnb   = (const float*)d_in[22];
    float* out = (float*)d_out;

    float* h     = symf(d_h);
    float* hl    = symf(d_hl);
    float* xg    = symf(d_xg);
    float* deg   = symf(d_deg);
    float* agg   = symf(d_agg);
    float* hr    = symf(d_hr);
    float* bns   = symf(d_bns);
    float* bnq   = symf(d_bnq);
    float* gates = symf(d_gates);
    float* lh    = symf(d_lh);
    float* lc    = symf(d_lc);
    float* cnt   = symf(d_cnt);
    float* hg    = symf(d_hg);
    float* z1    = symf(d_z1);
    float* z2    = symf(d_z2);

    const int TPB = 256;
    const dim3 blk(TPB);
    const int gridNC = (NN * C + TPB - 1) / TPB;
    const int rowsN  = (NN + 127) / 128;

    // degree (fixed across layers)
    k_zero<<<(NN + TPB - 1) / TPB, blk>>>(deg, NN);
    k_deg<<<(NE + TPB - 1) / TPB, blk>>>(dst);

    // -------- GMMConv layers --------
    const float* hin = x;
    for (int i = 0; i < LL; i++) {
        GA gxg = {hin, g + (size_t)i * C * KG * C, nullptr, nullptr, xg};
        tgemm<false, false, false, false>
            <<<dim3((KG * C) / 128, rowsN, 1), blk>>>(gxg, gxg, nullptr, NN, KG * C, C, 0);
        k_ew<<<(NE + TPB - 1) / TPB, blk>>>(ea, mu + i * KG * 2, sigma + i * KG * 2);
        k_zero<<<gridNC, blk>>>(agg, NN * C);
        k_scatter<<<(NE * 32 + TPB - 1) / TPB, blk>>>(src, dst);
        GA grt = {hin, root + (size_t)i * C * C, nullptr, nullptr, hr};
        tgemm<false, false, false, false>
            <<<dim3(1, rowsN, 1), blk>>>(grt, grt, nullptr, NN, C, C, 0);
        k_comb<<<gridNC, blk>>>(bias + i * C);
        k_zero<<<1, C>>>(bns, C);
        k_zero<<<1, C>>>(bnq, C);
        k_bnred<<<128, 128>>>();
        k_bnapp<<<gridNC, blk>>>(bng + i * C, bnb + i * C, hl + (size_t)i * NN * C,
                                 (i < LL - 1) ? 1 : 0);
        hin = h;
    }

    // -------- bidirectional LSTM JumpingKnowledge (both dirs batched) ------
    k_zero<<<(2 * NN * H + TPB - 1) / TPB, blk>>>(lc, 2 * NN * H);
    for (int s = 0; s < 5; s++) {
        int tf = s, tb = 4 - s;
        const float* xf = (tf == 0) ? x : (hl + (size_t)(tf - 1) * NN * C);
        const float* xb = (tb == 0) ? x : (hl + (size_t)(tb - 1) * NN * C);
        int K2 = (s > 0) ? H : 0;
        GA g0 = {xf, wih,                lh,               whh,
                 gates};
        GA g1 = {xb, wih + (size_t)H4 * C, lh + (size_t)NN * H, whh + (size_t)H4 * H,
                 gates + (size_t)NN * H4};
        tgemm<true, false, false, false>
            <<<dim3(H4 / 128, rowsN, 2), blk>>>(g0, g1, nullptr, NN, H4, C, K2);
        k_cellf<<<dim3(NN, 2), H>>>(bih, bhh, attw, s);
    }

    // attention softmax + weighted node representation
    k_nrep<<<NN, C>>>(x);

    // global mean pool
    k_zero<<<(NB + TPB - 1) / TPB, blk>>>(cnt, NB);
    k_zero<<<(NB * C + TPB - 1) / TPB, blk>>>(hg, NB * C);
    k_cnt<<<(NN + TPB - 1) / TPB, blk>>>(batch);
    k_pool<<<gridNC, blk>>>(batch);
    k_pdiv<<<(NB * C + TPB - 1) / TPB, blk>>>();

    // MLP + LayerNorm
    GA gp1 = {hg, p1w, nullptr, nullptr, z1};
    tgemm<false, false, true, true>
        <<<dim3(NHID / 128, NB / 128, 1), blk>>>(gp1, gp1, p1b, NB, NHID, C, 0);
    GA gp2 = {z1, p2w, nullptr, nullptr, z2};
    tgemm<false, false, false, true>
        <<<dim3(NOUT / 128, NB / 128, 1), blk>>>(gp2, gp2, p2b, NB, NOUT, NHID, 0);
    k_ln<<<NB, NOUT>>>(lng, lnb, out);
}